// round 9
// baseline (speedup 1.0000x reference)
#include <cuda_runtime.h>
#include <cuda_fp16.h>

// Poolpointsinterp: bilinear point sampling.
// NCHW fp32 -> NHWC fp16 scratch (64 MB, L2-resident) -> per-point gather.
// R8: 4 points/warp (MLP 16), streaming hints protect scratch in L2.

#define SPATIAL_SCALE 0.25f
#define Nn 8
#define Cc 256
#define Hh 128
#define Ww 128

#define PTS_PER_WARP 4

// 8*128*128*256 halves = 64 MB, NHWC: [((b*H+y)*W+x)*C + c]
__device__ __half g_nhwc[(size_t)Nn * Hh * Ww * Cc];

// ---------------------------------------------------------------------------
// Kernel 1: NCHW fp32 -> NHWC fp16 transpose.  (at DRAM floor; unchanged)
// grid = (C/32, N*H), block = 256.
// ---------------------------------------------------------------------------
__global__ void __launch_bounds__(256) transpose_kernel(const float* __restrict__ feat)
{
    __shared__ float tile[32][129];   // odd pad: scalar-STS/LDS conflict-free

    int cb = blockIdx.x * 32;
    int bh = blockIdx.y;              // b*H + y
    int b  = bh / Hh;
    int y  = bh % Hh;
    int tid = threadIdx.x;

    int c  = tid >> 3;
    int xq = tid & 7;
    const float4* src = (const float4*)(feat + (((size_t)b * Cc + cb + c) * Hh + y) * Ww);
    #pragma unroll
    for (int i = 0; i < 4; i++) {
        int f4 = i * 8 + xq;
        float4 v = __ldcs(src + f4);
        tile[c][f4 * 4 + 0] = v.x;
        tile[c][f4 * 4 + 1] = v.y;
        tile[c][f4 * 4 + 2] = v.z;
        tile[c][f4 * 4 + 3] = v.w;
    }
    __syncthreads();

    __half* dstbase = g_nhwc + (size_t)bh * Ww * Cc + cb;
    #pragma unroll
    for (int it = 0; it < 4; it++) {
        int idx = it * 256 + tid;
        int x = idx >> 3;
        int j = idx & 7;
        __half2 lo = __floats2half2_rn(tile[4 * j + 0][x], tile[4 * j + 1][x]);
        __half2 hi = __floats2half2_rn(tile[4 * j + 2][x], tile[4 * j + 3][x]);
        uint2 pack;
        pack.x = *(const unsigned*)&lo;
        pack.y = *(const unsigned*)&hi;
        *(uint2*)(dstbase + (size_t)x * Cc + 4 * j) = pack;
    }
}

// ---------------------------------------------------------------------------
// ROI math helper.
// ---------------------------------------------------------------------------
struct PointAddr {
    size_t base;   // uint4 index of corner (y_low, x_low)
    int dx, dy;    // uint4 deltas to high corners
    float w1, w2, w3, w4;
    bool valid;
};

__device__ __forceinline__ PointAddr roi_math(const float* __restrict__ rois, int p)
{
    PointAddr r;
    float rb = rois[p * 3 + 0];
    float rx = rois[p * 3 + 1];
    float ry = rois[p * 3 + 2];
    int bi = (int)rb;
    float x = rx * SPATIAL_SCALE;
    float y = ry * SPATIAL_SCALE;

    r.valid = (y >= -1.0f) & (y <= (float)Hh) & (x >= -1.0f) & (x <= (float)Ww);

    y = fmaxf(y, 0.0f);
    x = fmaxf(x, 0.0f);
    int y_low = (int)floorf(y);
    int x_low = (int)floorf(x);
    int dxs = 1, dys = 1;
    if (y_low >= Hh - 1) { y_low = Hh - 1; dys = 0; y = (float)y_low; }
    if (x_low >= Ww - 1) { x_low = Ww - 1; dxs = 0; x = (float)x_low; }

    float ly = y - (float)y_low;
    float lx = x - (float)x_low;
    float hy = 1.0f - ly;
    float hx = 1.0f - lx;
    r.w1 = hy * hx; r.w2 = hy * lx; r.w3 = ly * hx; r.w4 = ly * lx;

    r.base = ((size_t)(bi * Hh + y_low) * Ww + x_low) * 32;
    r.dx = dxs * 32;
    r.dy = dys * (Ww * 32);
    return r;
}

__device__ __forceinline__ void blend_store(
    const uint4& a, const uint4& b4, const uint4& c4, const uint4& d4,
    const PointAddr& r, float* __restrict__ out, int p, int t)
{
    const __half2* ah  = (const __half2*)&a;
    const __half2* bh2 = (const __half2*)&b4;
    const __half2* ch  = (const __half2*)&c4;
    const __half2* dh  = (const __half2*)&d4;

    float o[8];
    #pragma unroll
    for (int i = 0; i < 4; i++) {
        float2 f1 = __half22float2(ah[i]);
        float2 f2 = __half22float2(bh2[i]);
        float2 f3 = __half22float2(ch[i]);
        float2 f4 = __half22float2(dh[i]);
        o[2 * i + 0] = r.w1 * f1.x + r.w2 * f2.x + r.w3 * f3.x + r.w4 * f4.x;
        o[2 * i + 1] = r.w1 * f1.y + r.w2 * f2.y + r.w3 * f3.y + r.w4 * f4.y;
    }
    if (!r.valid) {
        #pragma unroll
        for (int i = 0; i < 8; i++) o[i] = 0.0f;
    }
    // Streaming stores: out is never re-read; don't evict scratch from L2.
    float4* dst = (float4*)(out + (size_t)p * Cc + t * 8);
    __stcs(dst + 0, make_float4(o[0], o[1], o[2], o[3]));
    __stcs(dst + 1, make_float4(o[4], o[5], o[6], o[7]));
}

// ---------------------------------------------------------------------------
// Kernel 2: gather. 4 points/warp; all 16 corner loads issued back-to-back
// (MLP=16) before any blending. block = 256 -> 32 points/block.
// ---------------------------------------------------------------------------
__global__ void __launch_bounds__(256) gather_kernel(
    const float* __restrict__ rois,
    float* __restrict__ out,
    int P)
{
    int w = blockIdx.x * 8 + (threadIdx.x >> 5);
    int pbase = w * PTS_PER_WARP;
    if (pbase >= P) return;
    int t = threadIdx.x & 31;

    PointAddr r[PTS_PER_WARP];
    #pragma unroll
    for (int k = 0; k < PTS_PER_WARP; k++) {
        int p = pbase + k;
        r[k] = roi_math(rois, p < P ? p : pbase);
    }

    const uint4* g = (const uint4*)g_nhwc;

    // Batch-issue all 16 independent loads.
    uint4 v[PTS_PER_WARP][4];
    #pragma unroll
    for (int k = 0; k < PTS_PER_WARP; k++) {
        const uint4* q = g + r[k].base + t;
        v[k][0] = q[0];
        v[k][1] = q[r[k].dx];
        v[k][2] = q[r[k].dy];
        v[k][3] = q[r[k].dy + r[k].dx];
    }

    #pragma unroll
    for (int k = 0; k < PTS_PER_WARP; k++) {
        int p = pbase + k;
        if (p < P)
            blend_store(v[k][0], v[k][1], v[k][2], v[k][3], r[k], out, p, t);
    }
}

extern "C" void kernel_launch(void* const* d_in, const int* in_sizes, int n_in,
                              void* d_out, int out_size)
{
    const float* feat = (const float*)d_in[0];
    const float* rois = (const float*)d_in[1];
    float* out = (float*)d_out;
    int P = in_sizes[1] / 3;

    dim3 tgrid(Cc / 32, Nn * Hh);
    transpose_kernel<<<tgrid, 256>>>(feat);

    int pts_per_block = 8 * PTS_PER_WARP;   // 8 warps/block
    gather_kernel<<<(P + pts_per_block - 1) / pts_per_block, 256>>>(rois, out, P);
}